// round 1
// baseline (speedup 1.0000x reference)
#include <cuda_runtime.h>

#define N_NODES 8192
#define PSI 64

// __device__ scratch (no allocations allowed)
__device__ float g_agg[N_NODES];   // per-node aggregate of edge features
__device__ float g_t[N_NODES];     // struct[n]^2
__device__ float g_s[N_NODES];     // per-node row score

// ---------------------------------------------------------------------------
// Kernel 0: zero the aggregation buffer (graph-capturable, no memset API)
// ---------------------------------------------------------------------------
__global__ void k_zero_agg() {
    int i = blockIdx.x * blockDim.x + threadIdx.x;
    if (i < N_NODES) g_agg[i] = 0.0f;
}

// ---------------------------------------------------------------------------
// Kernel 1: edge MLP + scatter-add by col.
// edge_feat = relu(v * w1 + b1) @ w2 + b2  (per scalar nonzero value)
// ---------------------------------------------------------------------------
__global__ void k_edge_scatter(const int* __restrict__ col,
                               const float* __restrict__ values,
                               const float* __restrict__ w1,
                               const float* __restrict__ b1,
                               const float* __restrict__ w2,
                               const float* __restrict__ b2,
                               int nnz) {
    __shared__ float sw1[PSI], sb1[PSI], sw2[PSI], sb2;
    if (threadIdx.x < PSI) {
        sw1[threadIdx.x] = w1[threadIdx.x];
        sb1[threadIdx.x] = b1[threadIdx.x];
        sw2[threadIdx.x] = w2[threadIdx.x];
    }
    if (threadIdx.x == 0) sb2 = b2[0];
    __syncthreads();

    int i = blockIdx.x * blockDim.x + threadIdx.x;
    if (i >= nnz) return;
    float v = values[i];
    float acc = sb2;
#pragma unroll
    for (int j = 0; j < PSI; j++) {
        float h = fmaf(v, sw1[j], sb1[j]);
        acc = fmaf(fmaxf(h, 0.0f), sw2[j], acc);
    }
    atomicAdd(&g_agg[col[i]], acc);
}

// ---------------------------------------------------------------------------
// Kernel 2: node MLP, store struct^2
// ---------------------------------------------------------------------------
__global__ void k_node_mlp(const float* __restrict__ w1,
                           const float* __restrict__ b1,
                           const float* __restrict__ w2,
                           const float* __restrict__ b2) {
    __shared__ float sw1[PSI], sb1[PSI], sw2[PSI], sb2;
    if (threadIdx.x < PSI) {
        sw1[threadIdx.x] = w1[threadIdx.x];
        sb1[threadIdx.x] = b1[threadIdx.x];
        sw2[threadIdx.x] = w2[threadIdx.x];
    }
    if (threadIdx.x == 0) sb2 = b2[0];
    __syncthreads();

    int i = blockIdx.x * blockDim.x + threadIdx.x;
    if (i >= N_NODES) return;
    float x = g_agg[i];
    float acc = sb2;
#pragma unroll
    for (int j = 0; j < PSI; j++) {
        float h = fmaf(x, sw1[j], sb1[j]);
        acc = fmaf(fmaxf(h, 0.0f), sw2[j], acc);
    }
    g_t[i] = acc * acc;
}

// ---------------------------------------------------------------------------
// Kernel 3: row score.  s[r] = sum_n adj[r,n]^2 * t[n]
// One 256-thread block per row; float4 streaming loads of the 32KB row.
// t[] (32 KB) is hot in L1/L2 across all 8192 blocks.
// This is the HBM-bound kernel: 256 MB of adj read exactly once.
// ---------------------------------------------------------------------------
__global__ __launch_bounds__(256) void k_row_score(const float* __restrict__ adj) {
    const int row = blockIdx.x;
    const float4* __restrict__ a =
        reinterpret_cast<const float4*>(adj + (size_t)row * N_NODES);
    const float4* __restrict__ tv = reinterpret_cast<const float4*>(g_t);

    float acc = 0.0f;
#pragma unroll 4
    for (int i = threadIdx.x; i < N_NODES / 4; i += 256) {
        float4 av = a[i];
        float4 tw = __ldg(&tv[i]);
        acc += av.x * av.x * tw.x;
        acc += av.y * av.y * tw.y;
        acc += av.z * av.z * tw.z;
        acc += av.w * av.w * tw.w;
    }
    // block reduction
#pragma unroll
    for (int off = 16; off > 0; off >>= 1)
        acc += __shfl_down_sync(0xffffffffu, acc, off);
    __shared__ float warp_sum[8];
    if ((threadIdx.x & 31) == 0) warp_sum[threadIdx.x >> 5] = acc;
    __syncthreads();
    if (threadIdx.x < 8) {
        float v = warp_sum[threadIdx.x];
#pragma unroll
        for (int off = 4; off > 0; off >>= 1)
            v += __shfl_down_sync(0xffu, v, off);
        if (threadIdx.x == 0) g_s[row] = v;
    }
}

// ---------------------------------------------------------------------------
// Kernel 4: gather per-edge output
// ---------------------------------------------------------------------------
__global__ void k_gather(const int* __restrict__ src_nodes,
                         float* __restrict__ out, int E) {
    int e = blockIdx.x * blockDim.x + threadIdx.x;
    if (e < E) out[e] = g_s[src_nodes[e]];
}

// ---------------------------------------------------------------------------
// launch
// Inputs (metadata order): col, values, adj, src_nodes,
//                          w1e, b1e, w2e, b2e, w1n, b1n, w2n, b2n
// ---------------------------------------------------------------------------
extern "C" void kernel_launch(void* const* d_in, const int* in_sizes, int n_in,
                              void* d_out, int out_size) {
    const int*   col       = (const int*)d_in[0];
    const float* values    = (const float*)d_in[1];
    const float* adj       = (const float*)d_in[2];
    const int*   src_nodes = (const int*)d_in[3];
    const float* w1e = (const float*)d_in[4];
    const float* b1e = (const float*)d_in[5];
    const float* w2e = (const float*)d_in[6];
    const float* b2e = (const float*)d_in[7];
    const float* w1n = (const float*)d_in[8];
    const float* b1n = (const float*)d_in[9];
    const float* w2n = (const float*)d_in[10];
    const float* b2n = (const float*)d_in[11];
    float* out = (float*)d_out;

    const int nnz = in_sizes[0];
    const int E   = in_sizes[3];

    k_zero_agg<<<(N_NODES + 255) / 256, 256>>>();
    k_edge_scatter<<<(nnz + 255) / 256, 256>>>(col, values, w1e, b1e, w2e, b2e, nnz);
    k_node_mlp<<<(N_NODES + 255) / 256, 256>>>(w1n, b1n, w2n, b2n);
    k_row_score<<<N_NODES, 256>>>(adj);
    k_gather<<<(E + 255) / 256, 256>>>(src_nodes, out, E);
}